// round 3
// baseline (speedup 1.0000x reference)
#include <cuda_runtime.h>
#include <cstdint>
#include <math.h>

// Problem constants
#define N_GLOB 256
#define M_GLOB 1024
#define D_GLOB 512
#define H_GLOB 512

// Tiling
#define E_SUB    32
#define S_SUB    8
#define P_TILE   256          // pairs per CTA = 32e x 8s
#define H_TILE   128          // H per pass (4 passes)
#define K_SLAB   32
#define THREADS  512
#define N_PHASES 64           // 4 passes * 16 k-slabs

// SMEM layout (float offsets)
#define ES_OFF   0            // [32][516]
#define SS_OFF   16512        // [8][516]
#define A_OFF    20640        // 2 x 8192 floats (frag-major: [pid(64)][lane(32)][4])
#define B_OFF    37024        // 2 x [32][136]
#define B1_OFF   45728        // 512
#define W2_OFF   46240        // 512
#define PART_OFF 46752        // 256
#define SMEM_FLOATS 47008
#define SMEM_BYTES  (SMEM_FLOATS * 4)   // 188032

__device__ __forceinline__ uint32_t smem_u32(const void* p) {
    uint32_t a;
    asm("{ .reg .u64 t; cvta.to.shared.u64 t, %1; cvt.u32.u64 %0, t; }" : "=r"(a) : "l"(p));
    return a;
}
__device__ __forceinline__ void cpa16(uint32_t s, const void* g) {
    asm volatile("cp.async.cg.shared.global [%0], [%1], 16;" :: "r"(s), "l"(g));
}
#define CP_COMMIT() asm volatile("cp.async.commit_group;" ::: "memory")
#define CP_WAIT0()  asm volatile("cp.async.wait_group 0;" ::: "memory")

__device__ __forceinline__ float tf32r(float f) {
    uint32_t r;
    asm("cvt.rna.tf32.f32 %0, %1;" : "=r"(r) : "f"(f));
    return __uint_as_float(r);
}

__global__ void __launch_bounds__(THREADS, 1)
support_mma_kernel(const float* __restrict__ E,   // [N, D]
                   const float* __restrict__ S,   // [M, D]
                   const float* __restrict__ W1,  // [D, H]
                   const float* __restrict__ B1,  // [H]
                   const float* __restrict__ W2,  // [H]
                   const float* __restrict__ B2,  // [1]
                   float* __restrict__ out)       // [N, M]
{
    extern __shared__ float sm[];
    const uint32_t smb = smem_u32(sm);
    const int tid  = threadIdx.x;
    const int wid  = tid >> 5;
    const int lane = tid & 31;
    const int warp_m = wid & 3;     // rows quadrant (64 rows)
    const int warp_n = wid >> 2;    // H quadrant (32 cols)

    const int n0 = blockIdx.y * E_SUB;
    const int m0 = blockIdx.x * S_SUB;

    // ---- prologue: stage E (32x512), S (8x512), B slab 0; b1/w2/partial ----
    #pragma unroll
    for (int i = tid; i < 4096; i += THREADS) {           // E: 32 rows x 128 chunks
        const int row = i >> 7, c = i & 127;
        cpa16(smb + (ES_OFF + row * 516 + c * 4) * 4, E + (size_t)(n0 + row) * D_GLOB + c * 4);
    }
    #pragma unroll
    for (int i = tid; i < 1024; i += THREADS) {           // S: 8 rows x 128 chunks
        const int row = i >> 7, c = i & 127;
        cpa16(smb + (SS_OFF + row * 516 + c * 4) * 4, S + (size_t)(m0 + row) * D_GLOB + c * 4);
    }
    #pragma unroll
    for (int i = tid; i < 1024; i += THREADS) {           // B slab 0 (k rows 0..31, H cols 0..127)
        const int row = i >> 5, c = i & 31;
        cpa16(smb + (B_OFF + row * 136 + c * 4) * 4, W1 + (size_t)row * H_GLOB + c * 4);
    }
    sm[B1_OFF + tid] = B1[tid];
    sm[W2_OFF + tid] = W2[tid];
    if (tid < 256) sm[PART_OFF + tid] = 0.f;
    CP_COMMIT();
    CP_WAIT0();
    __syncthreads();

    // ---- A builder: frag-major, slab ks -> buffer buf ----
    auto buildA = [&](int ks, int buf) {
        const int k0 = ks * K_SLAB;
        float* dst = sm + A_OFF + buf * 8192;
        #pragma unroll
        for (int iter = 0; iter < 4; ++iter) {
            const int pid  = iter * 16 + wid;       // 0..63 = (mt_g<<2)|kt
            const int mt_g = pid >> 2;
            const int kt   = pid & 3;
            const int k    = k0 + kt * 8 + (lane & 3);
            const int row0 = mt_g * 2;              // e-row for frag rows r<8
            const int sr   = lane >> 2;             // s-row (same for r and r+8)
            const float e00 = sm[ES_OFF + row0 * 516 + k];
            const float e01 = sm[ES_OFF + row0 * 516 + k + 4];
            const float e10 = sm[ES_OFF + (row0 + 1) * 516 + k];
            const float e11 = sm[ES_OFF + (row0 + 1) * 516 + k + 4];
            const float s0  = sm[SS_OFF + sr * 516 + k];
            const float s1  = sm[SS_OFF + sr * 516 + k + 4];
            float4 v;
            v.x = tf32r(fabsf(e00 - s0));   // reg0: (r,   k)
            v.y = tf32r(fabsf(e10 - s0));   // reg1: (r+8, k)
            v.z = tf32r(fabsf(e01 - s1));   // reg2: (r,   k+4)
            v.w = tf32r(fabsf(e11 - s1));   // reg3: (r+8, k+4)
            *(float4*)(dst + pid * 128 + lane * 4) = v;
        }
    };

    buildA(0, 0);

    float acc[4][4][4];
    float psum[8];
    #pragma unroll
    for (int i = 0; i < 8; ++i) psum[i] = 0.f;

    for (int g = 0; g < N_PHASES; ++g) {
        const int pass = g >> 4;
        const int slab = g & 15;
        const int buf  = g & 1;

        CP_WAIT0();
        __syncthreads();

        if (g < N_PHASES - 1) {
            const int ns = (g + 1) & 15;
            const int np = (g + 1) >> 4;
            const int nb = (g + 1) & 1;
            #pragma unroll
            for (int i = tid; i < 1024; i += THREADS) {
                const int row = i >> 5, c = i & 31;
                cpa16(smb + (B_OFF + nb * 4352 + row * 136 + c * 4) * 4,
                      W1 + (size_t)(ns * K_SLAB + row) * H_GLOB + np * H_TILE + c * 4);
            }
            CP_COMMIT();
            buildA(ns, nb);
        }

        if (slab == 0) {
            #pragma unroll
            for (int mt = 0; mt < 4; ++mt)
                #pragma unroll
                for (int nt = 0; nt < 4; ++nt)
                    #pragma unroll
                    for (int r = 0; r < 4; ++r) acc[mt][nt][r] = 0.f;
        }

        // ---- compute this slab ----
        {
            const float* bA = sm + A_OFF + buf * 8192;
            const float* bB = sm + B_OFF + buf * 4352;
            const int bk = (lane & 3);
            const int bn = warp_n * 32 + (lane >> 2);
            #pragma unroll
            for (int kt = 0; kt < 4; ++kt) {
                float4 af[4];
                #pragma unroll
                for (int mt = 0; mt < 4; ++mt)
                    af[mt] = *(const float4*)(bA + ((warp_m * 4 + mt) * 4 + kt) * 128 + lane * 4);
                float bq[4][2];
                const int krow = kt * 8 + bk;
                #pragma unroll
                for (int nt = 0; nt < 4; ++nt) {
                    bq[nt][0] = bB[krow * 136 + bn + nt * 8];
                    bq[nt][1] = bB[(krow + 4) * 136 + bn + nt * 8];
                }
                #pragma unroll
                for (int mt = 0; mt < 4; ++mt)
                    #pragma unroll
                    for (int nt = 0; nt < 4; ++nt) {
                        asm volatile(
                            "mma.sync.aligned.m16n8k8.row.col.f32.tf32.tf32.f32 "
                            "{%0,%1,%2,%3}, {%4,%5,%6,%7}, {%8,%9}, {%0,%1,%2,%3};\n"
                            : "+f"(acc[mt][nt][0]), "+f"(acc[mt][nt][1]),
                              "+f"(acc[mt][nt][2]), "+f"(acc[mt][nt][3])
                            : "r"(__float_as_uint(af[mt].x)), "r"(__float_as_uint(af[mt].y)),
                              "r"(__float_as_uint(af[mt].z)), "r"(__float_as_uint(af[mt].w)),
                              "r"(__float_as_uint(bq[nt][0])), "r"(__float_as_uint(bq[nt][1])));
                    }
            }
        }

        // ---- pass epilogue: relu(+b1) * w2, fold into psum ----
        if (slab == 15) {
            #pragma unroll
            for (int mt = 0; mt < 4; ++mt)
                #pragma unroll
                for (int nt = 0; nt < 4; ++nt) {
                    const int jg = pass * H_TILE + warp_n * 32 + nt * 8 + (lane & 3) * 2;
                    const float b1a = sm[B1_OFF + jg], b1b = sm[B1_OFF + jg + 1];
                    const float w2a = sm[W2_OFF + jg], w2b = sm[W2_OFF + jg + 1];
                    const float h0 = fmaxf(acc[mt][nt][0] + b1a, 0.f);
                    const float h1 = fmaxf(acc[mt][nt][1] + b1b, 0.f);
                    const float h2 = fmaxf(acc[mt][nt][2] + b1a, 0.f);
                    const float h3 = fmaxf(acc[mt][nt][3] + b1b, 0.f);
                    psum[mt * 2 + 0] += h0 * w2a + h1 * w2b;
                    psum[mt * 2 + 1] += h2 * w2a + h3 * w2b;
                }
        }
    }

    // ---- reduce across lane&3 quad, then across n-warps via smem atomics ----
    #pragma unroll
    for (int i = 0; i < 8; ++i) {
        psum[i] += __shfl_xor_sync(0xffffffffu, psum[i], 1);
        psum[i] += __shfl_xor_sync(0xffffffffu, psum[i], 2);
    }
    if ((lane & 3) == 0) {
        const int r = lane >> 2;
        #pragma unroll
        for (int mt = 0; mt < 4; ++mt) {
            atomicAdd(&sm[PART_OFF + warp_m * 64 + mt * 16 + r],     psum[mt * 2 + 0]);
            atomicAdd(&sm[PART_OFF + warp_m * 64 + mt * 16 + r + 8], psum[mt * 2 + 1]);
        }
    }
    __syncthreads();

    if (tid < P_TILE) {
        const float logit = sm[PART_OFF + tid] + B2[0];
        const int n = n0 + (tid >> 3);
        const int m = m0 + (tid & 7);
        out[(size_t)n * M_GLOB + m] = 1.f / (1.f + expf(-logit));
    }
}

extern "C" void kernel_launch(void* const* d_in, const int* in_sizes, int n_in,
                              void* d_out, int out_size)
{
    const float* E  = (const float*)d_in[0];
    const float* S  = (const float*)d_in[1];
    const float* W1 = (const float*)d_in[2];
    const float* B1 = (const float*)d_in[3];
    const float* W2 = (const float*)d_in[4];
    const float* B2 = (const float*)d_in[5];
    float* out = (float*)d_out;

    cudaFuncSetAttribute(support_mma_kernel,
                         cudaFuncAttributeMaxDynamicSharedMemorySize, SMEM_BYTES);

    dim3 grid(M_GLOB / S_SUB, N_GLOB / E_SUB);   // (128, 8) = 1024 CTAs
    support_mma_kernel<<<grid, THREADS, SMEM_BYTES>>>(E, S, W1, B1, W2, B2, out);
}

// round 5
// speedup vs baseline: 2.2329x; 2.2329x over previous
#include <cuda_runtime.h>
#include <cuda_fp16.h>
#include <cstdint>
#include <math.h>

// Problem constants
#define N_GLOB 256
#define M_GLOB 1024
#define D_GLOB 512
#define H_GLOB 512

// Tiling
#define E_SUB    32
#define S_SUB    8
#define P_TILE   256          // pairs per CTA = 32e x 8s
#define H_TILE   128          // H per pass (4 passes)
#define K_SLAB   32           // K per phase (= 2 x k16)
#define THREADS  512
#define N_PHASES 64           // 4 passes * 16 k-slabs

// SMEM layout (byte offsets)
#define ES_OFF   0            // [32][516] f32
#define SS_OFF   66048        // [8][516]  f32
#define A_OFF    82560        // 2 x 16384 B  (frag-major fp16: [pid(32)][lane(32)][uint4])
#define B_OFF    115328       // 2 x [128][40] half (10240 B each)
#define B1_OFF   135808       // 512 f32
#define W2_OFF   137856       // 512 f32
#define PART_OFF 139904       // 256 f32
#define SMEM_BYTES 140928

#define B_PADH   40           // halfs per B row (32 data + 8 pad) -> conflict-free frags

__device__ static __half g_W1T[H_GLOB * D_GLOB];   // W1 transposed [h][k], fp16

__device__ __forceinline__ uint32_t smem_u32(const void* p) {
    uint32_t a;
    asm("{ .reg .u64 t; cvta.to.shared.u64 t, %1; cvt.u32.u64 %0, t; }" : "=r"(a) : "l"(p));
    return a;
}
__device__ __forceinline__ void cpa16(uint32_t s, const void* g) {
    asm volatile("cp.async.cg.shared.global [%0], [%1], 16;" :: "r"(s), "l"(g));
}
#define CP_COMMIT() asm volatile("cp.async.commit_group;" ::: "memory")
#define CP_WAIT0()  asm volatile("cp.async.wait_group 0;" ::: "memory")

// pack two f32 (rounded rn to fp16) into one u32 lane register
__device__ __forceinline__ uint32_t pack_h2(float lo, float hi) {
    const __half2 h = __floats2half2_rn(lo, hi);
    uint32_t u;
    __builtin_memcpy(&u, &h, 4);
    return u;
}

// ---- pre-kernel: W1 [D][H] f32  ->  g_W1T [H][D] fp16 ----
__global__ void convert_w1_kernel(const float* __restrict__ W1) {
    __shared__ float tile[32][33];
    const int kx = blockIdx.x * 32;   // k tile
    const int hx = blockIdx.y * 32;   // h tile
    const int x = threadIdx.x, y = threadIdx.y;   // 32 x 8
    #pragma unroll
    for (int i = 0; i < 32; i += 8)
        tile[y + i][x] = W1[(size_t)(kx + y + i) * H_GLOB + hx + x];
    __syncthreads();
    #pragma unroll
    for (int i = 0; i < 32; i += 8)
        g_W1T[(size_t)(hx + y + i) * D_GLOB + kx + x] = __float2half(tile[x][y + i]);
}

__global__ void __launch_bounds__(THREADS, 1)
support_fp16_kernel(const float* __restrict__ E,   // [N, D]
                    const float* __restrict__ S,   // [M, D]
                    const float* __restrict__ B1,  // [H]
                    const float* __restrict__ W2,  // [H]
                    const float* __restrict__ B2,  // [1]
                    float* __restrict__ out)       // [N, M]
{
    extern __shared__ char smem[];
    float* smE   = (float*)(smem + ES_OFF);
    float* smS   = (float*)(smem + SS_OFF);
    float* smB1  = (float*)(smem + B1_OFF);
    float* smW2  = (float*)(smem + W2_OFF);
    float* smP   = (float*)(smem + PART_OFF);
    const uint32_t smb = smem_u32(smem);

    const int tid  = threadIdx.x;
    const int wid  = tid >> 5;
    const int lane = tid & 31;
    const int warp_m = wid & 3;     // 64-row quadrant
    const int warp_n = wid >> 2;    // 32-col H quadrant

    const int n0 = blockIdx.y * E_SUB;
    const int m0 = blockIdx.x * S_SUB;

    // ---- prologue: stage E (32x512), S (8x512), B slab 0, b1/w2 ----
    #pragma unroll
    for (int i = tid; i < 4096; i += THREADS) {           // E
        const int row = i >> 7, c = i & 127;
        cpa16(smb + ES_OFF + (row * 516 + c * 4) * 4, E + (size_t)(n0 + row) * D_GLOB + c * 4);
    }
    #pragma unroll
    for (int i = tid; i < 1024; i += THREADS) {           // S
        const int row = i >> 7, c = i & 127;
        cpa16(smb + SS_OFF + (row * 516 + c * 4) * 4, S + (size_t)(m0 + row) * D_GLOB + c * 4);
    }
    {   // B slab 0: pass 0, kslab 0 -> buf 0 : [128 h][32 k] fp16
        const int h = tid >> 2, q = tid & 3;   // 512 threads cover 512 chunks
        cpa16(smb + B_OFF + h * (B_PADH * 2) + q * 16,
              g_W1T + (size_t)h * D_GLOB + q * 8);
    }
    smB1[tid] = B1[tid];
    smW2[tid] = W2[tid];
    if (tid < 256) smP[tid] = 0.f;
    CP_COMMIT();
    CP_WAIT0();
    __syncthreads();

    // ---- A builder: frag-major fp16, slab ks -> buffer buf ----
    // pid = mt_g*2 + kt  (mt_g: 16-row tile 0..15, kt: k16 step 0..1)
    auto buildA = [&](int ks, int buf) {
        const int k0 = ks * K_SLAB;
        char* dst = smem + A_OFF + buf * 16384;
        #pragma unroll
        for (int iter = 0; iter < 2; ++iter) {
            const int pid  = iter * 16 + wid;    // 0..31
            const int mt_g = pid >> 1;
            const int kt   = pid & 1;
            const int c    = lane & 3;
            const int r    = lane >> 2;          // 0..7 (= s-row)
            const int row0 = mt_g * 2;           // e-row for frag rows r
            const int kb   = k0 + kt * 16 + c * 2;
            const float2 e0  = *(const float2*)(smE + row0 * 516 + kb);
            const float2 e0b = *(const float2*)(smE + row0 * 516 + kb + 8);
            const float2 e1  = *(const float2*)(smE + (row0 + 1) * 516 + kb);
            const float2 e1b = *(const float2*)(smE + (row0 + 1) * 516 + kb + 8);
            const float2 s0  = *(const float2*)(smS + r * 516 + kb);
            const float2 s0b = *(const float2*)(smS + r * 516 + kb + 8);
            uint4 v;
            v.x = pack_h2(fabsf(e0.x  - s0.x),  fabsf(e0.y  - s0.y));
            v.y = pack_h2(fabsf(e1.x  - s0.x),  fabsf(e1.y  - s0.y));
            v.z = pack_h2(fabsf(e0b.x - s0b.x), fabsf(e0b.y - s0b.y));
            v.w = pack_h2(fabsf(e1b.x - s0b.x), fabsf(e1b.y - s0b.y));
            *(uint4*)(dst + pid * 512 + lane * 16) = v;
        }
    };

    buildA(0, 0);

    float acc[4][4][4];
    float psum[8];
    #pragma unroll
    for (int i = 0; i < 8; ++i) psum[i] = 0.f;

    for (int g = 0; g < N_PHASES; ++g) {
        const int pass = g >> 4;
        const int slab = g & 15;
        const int buf  = g & 1;

        CP_WAIT0();
        __syncthreads();

        if (g < N_PHASES - 1) {
            const int ns = (g + 1) & 15;
            const int np = (g + 1) >> 4;
            const int nb = (g + 1) & 1;
            {   // next B slab: [128 h][32 k] fp16 from g_W1T
                const int h = tid >> 2, q = tid & 3;
                cpa16(smb + B_OFF + nb * 10240 + h * (B_PADH * 2) + q * 16,
                      g_W1T + (size_t)(np * H_TILE + h) * D_GLOB + ns * K_SLAB + q * 8);
            }
            CP_COMMIT();
            buildA(ns, nb);
        }

        if (slab == 0) {
            #pragma unroll
            for (int mt = 0; mt < 4; ++mt)
                #pragma unroll
                for (int nt = 0; nt < 4; ++nt)
                    #pragma unroll
                    for (int r = 0; r < 4; ++r) acc[mt][nt][r] = 0.f;
        }

        // ---- compute this slab: 2 kt steps of m16n8k16 ----
        {
            const char*   bA = smem + A_OFF + buf * 16384;
            const __half* bB = (const __half*)(smem + B_OFF + buf * 10240);
            const int c  = lane & 3;
            const int bn = warp_n * 32 + (lane >> 2);
            #pragma unroll
            for (int kt = 0; kt < 2; ++kt) {
                uint4 af[4];
                #pragma unroll
                for (int mt = 0; mt < 4; ++mt)
                    af[mt] = *(const uint4*)(bA + (((warp_m * 4 + mt) * 2 + kt) * 32 + lane) * 16);
                uint32_t bq[4][2];
                const int kk = kt * 16 + c * 2;
                #pragma unroll
                for (int nt = 0; nt < 4; ++nt) {
                    bq[nt][0] = *(const uint32_t*)(bB + (bn + nt * 8) * B_PADH + kk);
                    bq[nt][1] = *(const uint32_t*)(bB + (bn + nt * 8) * B_PADH + kk + 8);
                }
                #pragma unroll
                for (int mt = 0; mt < 4; ++mt)
                    #pragma unroll
                    for (int nt = 0; nt < 4; ++nt) {
                        asm volatile(
                            "mma.sync.aligned.m16n8k16.row.col.f32.f16.f16.f32 "
                            "{%0,%1,%2,%3}, {%4,%5,%6,%7}, {%8,%9}, {%0,%1,%2,%3};\n"
                            : "+f"(acc[mt][nt][0]), "+f"(acc[mt][nt][1]),
                              "+f"(acc[mt][nt][2]), "+f"(acc[mt][nt][3])
                            : "r"(af[mt].x), "r"(af[mt].y), "r"(af[mt].z), "r"(af[mt].w),
                              "r"(bq[nt][0]), "r"(bq[nt][1]));
                    }
            }
        }

        // ---- pass epilogue: relu(+b1) * w2, fold into psum ----
        if (slab == 15) {
            #pragma unroll
            for (int mt = 0; mt < 4; ++mt)
                #pragma unroll
                for (int nt = 0; nt < 4; ++nt) {
                    const int jg = pass * H_TILE + warp_n * 32 + nt * 8 + (lane & 3) * 2;
                    const float b1a = smB1[jg], b1b = smB1[jg + 1];
                    const float w2a = smW2[jg], w2b = smW2[jg + 1];
                    const float h0 = fmaxf(acc[mt][nt][0] + b1a, 0.f);
                    const float h1 = fmaxf(acc[mt][nt][1] + b1b, 0.f);
                    const float h2 = fmaxf(acc[mt][nt][2] + b1a, 0.f);
                    const float h3 = fmaxf(acc[mt][nt][3] + b1b, 0.f);
                    psum[mt * 2 + 0] += h0 * w2a + h1 * w2b;
                    psum[mt * 2 + 1] += h2 * w2a + h3 * w2b;
                }
        }
    }

    // ---- reduce across quad (cols), then across n-warps via smem atomics ----
    #pragma unroll
    for (int i = 0; i < 8; ++i) {
        psum[i] += __shfl_xor_sync(0xffffffffu, psum[i], 1);
        psum[i] += __shfl_xor_sync(0xffffffffu, psum[i], 2);
    }
    if ((lane & 3) == 0) {
        const int r = lane >> 2;
        #pragma unroll
        for (int mt = 0; mt < 4; ++mt) {
            atomicAdd(&smP[warp_m * 64 + mt * 16 + r],     psum[mt * 2 + 0]);
            atomicAdd(&smP[warp_m * 64 + mt * 16 + r + 8], psum[mt * 2 + 1]);
        }
    }
    __syncthreads();

    if (tid < P_TILE) {
        const float logit = smP[tid] + B2[0];
        const int n = n0 + (tid >> 3);
        const int m = m0 + (tid & 7);
        out[(size_t)n * M_GLOB + m] = 1.f / (1.f + expf(-logit));
    }
}

extern "C" void kernel_launch(void* const* d_in, const int* in_sizes, int n_in,
                              void* d_out, int out_size)
{
    const float* E  = (const float*)d_in[0];
    const float* S  = (const float*)d_in[1];
    const float* W1 = (const float*)d_in[2];
    const float* B1 = (const float*)d_in[3];
    const float* W2 = (const float*)d_in[4];
    const float* B2 = (const float*)d_in[5];
    float* out = (float*)d_out;

    // 1) transpose+convert W1 -> g_W1T (fp16, [h][k])
    convert_w1_kernel<<<dim3(16, 16), dim3(32, 8)>>>(W1);

    // 2) fused pairwise-MLP kernel
    cudaFuncSetAttribute(support_fp16_kernel,
                         cudaFuncAttributeMaxDynamicSharedMemorySize, SMEM_BYTES);
    dim3 grid(M_GLOB / S_SUB, N_GLOB / E_SUB);   // (128, 8) = 1024 CTAs
    support_fp16_kernel<<<grid, THREADS, SMEM_BYTES>>>(E, S, B1, W2, B2, out);
}

// round 6
// speedup vs baseline: 2.7052x; 1.2115x over previous
#include <cuda_runtime.h>
#include <cuda_fp16.h>
#include <cstdint>
#include <math.h>

// Problem constants
#define N_GLOB 256
#define M_GLOB 1024
#define D_GLOB 512
#define H_GLOB 512

// Tiling
#define E_SUB    32
#define S_SUB    8
#define P_TILE   256          // pairs per CTA = 32e x 8s
#define H_TILE   128          // H per pass (4 passes)
#define K_SLAB   32           // K per phase
#define N_PHASES 64           // 4 passes * 16 k-slabs
#define N_STAGES 4

#define THREADS  576          // 512 consumers (16 warps) + 64 producers (2 warps)
#define NCONS    512

// SMEM layout (byte offsets)
#define MBAR_OFF 0            // full[4] @ 0,8,16,24 ; empty[4] @ 32,40,48,56
#define B1_OFF   128          // 512 f32
#define W2_OFF   2176         // 512 f32
#define PART_OFF 4224         // 256 f32
#define ES_OFF   5248         // [32][520] half  (33280 B)
#define SS_OFF   38528        // [8][520] half   (8320 B)
#define A_OFF    46848        // 4 x 16384 B (frag-major: [pid(32)][lane(32)][16B])
#define B_OFF    112384       // 4 x [128][40] half (10240 B each)
#define SMEM_BYTES 153344

#define B_PADH   40           // halfs per B row (32 data + 8 pad), 80 B, 16B-aligned

__device__ static __half g_W1T[H_GLOB * D_GLOB];   // W1 transposed [h][k], fp16

__device__ __forceinline__ uint32_t smem_u32(const void* p) {
    uint32_t a;
    asm("{ .reg .u64 t; cvta.to.shared.u64 t, %1; cvt.u32.u64 %0, t; }" : "=r"(a) : "l"(p));
    return a;
}
__device__ __forceinline__ void cpa16(uint32_t s, const void* g) {
    asm volatile("cp.async.cg.shared.global [%0], [%1], 16;" :: "r"(s), "l"(g));
}
#define MBARRIER_INIT(addr, cnt) \
    asm volatile("mbarrier.init.shared.b64 [%0], %1;" :: "r"((uint32_t)(addr)), "r"((uint32_t)(cnt)) : "memory")
#define MBARRIER_ARRIVE(addr) \
    asm volatile("mbarrier.arrive.shared.b64 _, [%0];" :: "r"((uint32_t)(addr)) : "memory")
#define CPASYNC_MBAR_ARRIVE(addr) \
    asm volatile("cp.async.mbarrier.arrive.noinc.shared.b64 [%0];" :: "r"((uint32_t)(addr)) : "memory")
#define MBARRIER_WAIT_PARITY(addr, parity) do { \
    uint32_t _m = (uint32_t)(addr); uint32_t _p = (uint32_t)(parity); uint32_t _d; \
    asm volatile("{\n\t.reg .pred p;\n\t" \
        "mbarrier.try_wait.parity.acquire.cta.shared::cta.b64 p, [%1], %2;\n\t" \
        "selp.b32 %0, 1, 0, p;\n\t}" : "=r"(_d) : "r"(_m), "r"(_p) : "memory"); \
    if (!_d) { \
        asm volatile("{\n\t.reg .pred P1;\n\t" \
            "WL_%=:\n\t" \
            "mbarrier.try_wait.parity.acquire.cta.shared::cta.b64 P1, [%0], %1, 0x989680;\n\t" \
            "@P1 bra.uni WD_%=;\n\t" \
            "bra.uni WL_%=;\n\t" \
            "WD_%=:\n\t}" :: "r"(_m), "r"(_p) : "memory"); \
    } } while (0)

__device__ __forceinline__ uint32_t h2_u32(__half2 h) {
    uint32_t u;
    __builtin_memcpy(&u, &h, 4);
    return u;
}

// ---- pre-kernel: W1 [D][H] f32  ->  g_W1T [H][D] fp16 ----
__global__ void convert_w1_kernel(const float* __restrict__ W1) {
    __shared__ float tile[32][33];
    const int kx = blockIdx.x * 32;
    const int hx = blockIdx.y * 32;
    const int x = threadIdx.x, y = threadIdx.y;   // 32 x 8
    #pragma unroll
    for (int i = 0; i < 32; i += 8)
        tile[y + i][x] = W1[(size_t)(kx + y + i) * H_GLOB + hx + x];
    __syncthreads();
    #pragma unroll
    for (int i = 0; i < 32; i += 8)
        g_W1T[(size_t)(hx + y + i) * D_GLOB + kx + x] = __float2half(tile[x][y + i]);
}

__global__ void __launch_bounds__(THREADS, 1)
support_ws_kernel(const float* __restrict__ E,   // [N, D]
                  const float* __restrict__ S,   // [M, D]
                  const float* __restrict__ B1,  // [H]
                  const float* __restrict__ W2,  // [H]
                  const float* __restrict__ B2,  // [1]
                  float* __restrict__ out)       // [N, M]
{
    extern __shared__ char smem[];
    __half* smE  = (__half*)(smem + ES_OFF);
    __half* smS  = (__half*)(smem + SS_OFF);
    float*  smB1 = (float*)(smem + B1_OFF);
    float*  smW2 = (float*)(smem + W2_OFF);
    float*  smP  = (float*)(smem + PART_OFF);
    const uint32_t smb = smem_u32(smem);

    const int tid  = threadIdx.x;
    const int wid  = tid >> 5;
    const int lane = tid & 31;

    const int n0 = blockIdx.y * E_SUB;
    const int m0 = blockIdx.x * S_SUB;

    // ---- prologue (all threads): mbarriers, E/S fp16 staging, b1/w2, partials ----
    if (tid == 0) {
        #pragma unroll
        for (int s = 0; s < N_STAGES; ++s) {
            MBARRIER_INIT(smb + MBAR_OFF + s * 8, 128);        // full: 64 STS + 64 cp.async
            MBARRIER_INIT(smb + MBAR_OFF + 32 + s * 8, NCONS); // empty: 512 consumer arrives
        }
    }
    // E: 32 rows x 512 -> fp16 [row][520]
    for (int i = tid; i < 8192; i += THREADS) {       // float2 chunks
        const int row = i >> 8, c = i & 255;
        const float2 v = *(const float2*)(E + (size_t)(n0 + row) * D_GLOB + c * 2);
        *(__half2*)(smE + row * 520 + c * 2) = __floats2half2_rn(v.x, v.y);
    }
    // S: 8 rows x 512
    for (int i = tid; i < 2048; i += THREADS) {
        const int row = i >> 8, c = i & 255;
        const float2 v = *(const float2*)(S + (size_t)(m0 + row) * D_GLOB + c * 2);
        *(__half2*)(smS + row * 520 + c * 2) = __floats2half2_rn(v.x, v.y);
    }
    if (tid < 512) { smB1[tid] = B1[tid]; smW2[tid] = W2[tid]; }
    if (tid < 256) smP[tid] = 0.f;
    __syncthreads();

    if (wid >= 16) {
        // ================= PRODUCER (2 warps, 64 threads) =================
        const int pw = wid - 16;          // 0..1
        const int pt = tid - NCONS;       // 0..63
        const int c  = lane & 3;
        const int r  = lane >> 2;

        for (int p = 0; p < N_PHASES; ++p) {
            const int st   = p & 3;
            const int ph   = (p >> 2) & 1;
            const int slab = p & 15;
            const int pass = p >> 4;

            MBARRIER_WAIT_PARITY(smb + MBAR_OFF + 32 + st * 8, ph ^ 1);  // wait empty

            // --- build A frags (fp16) into stage st ---
            char* stA = smem + A_OFF + st * 16384;
            #pragma unroll
            for (int j = 0; j < 16; ++j) {
                const int pid  = j * 2 + pw;       // 0..31
                const int mt_g = pid >> 1;
                const int kt   = pid & 1;
                const int row0 = mt_g * 2;
                const int kb   = slab * 32 + kt * 16 + c * 2;
                const __half2 e0  = *(const __half2*)(smE + row0 * 520 + kb);
                const __half2 e0b = *(const __half2*)(smE + row0 * 520 + kb + 8);
                const __half2 e1  = *(const __half2*)(smE + (row0 + 1) * 520 + kb);
                const __half2 e1b = *(const __half2*)(smE + (row0 + 1) * 520 + kb + 8);
                const __half2 s0  = *(const __half2*)(smS + r * 520 + kb);
                const __half2 s0b = *(const __half2*)(smS + r * 520 + kb + 8);
                uint4 v;
                v.x = h2_u32(__habs2(__hsub2(e0,  s0)));
                v.y = h2_u32(__habs2(__hsub2(e1,  s0)));
                v.z = h2_u32(__habs2(__hsub2(e0b, s0b)));
                v.w = h2_u32(__habs2(__hsub2(e1b, s0b)));
                *(uint4*)(stA + pid * 512 + lane * 16) = v;
            }
            MBARRIER_ARRIVE(smb + MBAR_OFF + st * 8);   // A visible (release)

            // --- B slab cp.async into stage st: [128 h][32 k] fp16 ---
            #pragma unroll
            for (int j = 0; j < 8; ++j) {
                const int idx = pt + j * 64;            // 0..511
                const int h = idx >> 2, q = idx & 3;
                cpa16(smb + B_OFF + st * 10240 + h * 80 + q * 16,
                      g_W1T + (size_t)(pass * H_TILE + h) * D_GLOB + slab * K_SLAB + q * 8);
            }
            CPASYNC_MBAR_ARRIVE(smb + MBAR_OFF + st * 8);  // arrives when cp.asyncs land
        }
    } else {
        // ================= CONSUMER (16 warps, 512 threads) =================
        const int warp_m = wid & 3;
        const int warp_n = wid >> 2;
        const int c  = lane & 3;
        const int bn = warp_n * 32 + (lane >> 2);

        float acc[4][4][4];
        float psum[8];
        #pragma unroll
        for (int i = 0; i < 8; ++i) psum[i] = 0.f;

        for (int p = 0; p < N_PHASES; ++p) {
            const int st   = p & 3;
            const int ph   = (p >> 2) & 1;
            const int slab = p & 15;
            const int pass = p >> 4;

            MBARRIER_WAIT_PARITY(smb + MBAR_OFF + st * 8, ph);   // wait full

            if (slab == 0) {
                #pragma unroll
                for (int mt = 0; mt < 4; ++mt)
                    #pragma unroll
                    for (int nt = 0; nt < 4; ++nt)
                        #pragma unroll
                        for (int q = 0; q < 4; ++q) acc[mt][nt][q] = 0.f;
            }

            const char*   bA = smem + A_OFF + st * 16384;
            const __half* bB = (const __half*)(smem + B_OFF + st * 10240);
            #pragma unroll
            for (int kt = 0; kt < 2; ++kt) {
                uint4 af[4];
                #pragma unroll
                for (int mt = 0; mt < 4; ++mt)
                    af[mt] = *(const uint4*)(bA + (((warp_m * 4 + mt) * 2 + kt) * 32 + lane) * 16);
                uint32_t bq[4][2];
                const int kk = kt * 16 + c * 2;
                #pragma unroll
                for (int nt = 0; nt < 4; ++nt) {
                    bq[nt][0] = *(const uint32_t*)(bB + (bn + nt * 8) * B_PADH + kk);
                    bq[nt][1] = *(const uint32_t*)(bB + (bn + nt * 8) * B_PADH + kk + 8);
                }
                #pragma unroll
                for (int mt = 0; mt < 4; ++mt)
                    #pragma unroll
                    for (int nt = 0; nt < 4; ++nt) {
                        asm volatile(
                            "mma.sync.aligned.m16n8k16.row.col.f32.f16.f16.f32 "
                            "{%0,%1,%2,%3}, {%4,%5,%6,%7}, {%8,%9}, {%0,%1,%2,%3};\n"
                            : "+f"(acc[mt][nt][0]), "+f"(acc[mt][nt][1]),
                              "+f"(acc[mt][nt][2]), "+f"(acc[mt][nt][3])
                            : "r"(af[mt].x), "r"(af[mt].y), "r"(af[mt].z), "r"(af[mt].w),
                              "r"(bq[nt][0]), "r"(bq[nt][1]));
                    }
            }
            MBARRIER_ARRIVE(smb + MBAR_OFF + 32 + st * 8);   // stage consumed

            if (slab == 15) {
                #pragma unroll
                for (int mt = 0; mt < 4; ++mt)
                    #pragma unroll
                    for (int nt = 0; nt < 4; ++nt) {
                        const int jg = pass * H_TILE + warp_n * 32 + nt * 8 + c * 2;
                        const float b1a = smB1[jg], b1b = smB1[jg + 1];
                        const float w2a = smW2[jg], w2b = smW2[jg + 1];
                        const float h0 = fmaxf(acc[mt][nt][0] + b1a, 0.f);
                        const float h1 = fmaxf(acc[mt][nt][1] + b1b, 0.f);
                        const float h2 = fmaxf(acc[mt][nt][2] + b1a, 0.f);
                        const float h3 = fmaxf(acc[mt][nt][3] + b1b, 0.f);
                        psum[mt * 2 + 0] += h0 * w2a + h1 * w2b;
                        psum[mt * 2 + 1] += h2 * w2a + h3 * w2b;
                    }
            }
        }

        // reduce across quad (k-cols of frag), then across n-warps via smem atomics
        #pragma unroll
        for (int i = 0; i < 8; ++i) {
            psum[i] += __shfl_xor_sync(0xffffffffu, psum[i], 1);
            psum[i] += __shfl_xor_sync(0xffffffffu, psum[i], 2);
        }
        if (c == 0) {
            const int r = lane >> 2;
            #pragma unroll
            for (int mt = 0; mt < 4; ++mt) {
                atomicAdd(&smP[warp_m * 64 + mt * 16 + r],     psum[mt * 2 + 0]);
                atomicAdd(&smP[warp_m * 64 + mt * 16 + r + 8], psum[mt * 2 + 1]);
            }
        }
    }

    __syncthreads();
    if (tid < P_TILE) {
        const float logit = smP[tid] + B2[0];
        const int n = n0 + (tid >> 3);
        const int m = m0 + (tid & 7);
        out[(size_t)n * M_GLOB + m] = 1.f / (1.f + expf(-logit));
    }
}

extern "C" void kernel_launch(void* const* d_in, const int* in_sizes, int n_in,
                              void* d_out, int out_size)
{
    const float* E  = (const float*)d_in[0];
    const float* S  = (const float*)d_in[1];
    const float* W1 = (const float*)d_in[2];
    const float* B1 = (const float*)d_in[3];
    const float* W2 = (const float*)d_in[4];
    const float* B2 = (const float*)d_in[5];
    float* out = (float*)d_out;

    convert_w1_kernel<<<dim3(16, 16), dim3(32, 8)>>>(W1);

    cudaFuncSetAttribute(support_ws_kernel,
                         cudaFuncAttributeMaxDynamicSharedMemorySize, SMEM_BYTES);
    dim3 grid(M_GLOB / S_SUB, N_GLOB / E_SUB);   // (128, 8) = 1024 CTAs
    support_ws_kernel<<<grid, THREADS, SMEM_BYTES>>>(E, S, B1, W2, B2, out);
}